// round 16
// baseline (speedup 1.0000x reference)
#include <cuda_runtime.h>

#define K 8
#define TBL 2048
#define THREADS 256
#define BLOCKS_PER_SM 4
#define NBLOCKS (148 * BLOCKS_PER_SM)
#define XMIN_F (-6.0f)
#define XRANGE_F 12.0f
#define LOG2PI 1.8378770664093453f
#define LOG2E  1.4426950408889634f

__device__ __forceinline__ float fast_ex2(float v) {
    float r; asm("ex2.approx.ftz.f32 %0, %1;" : "=f"(r) : "f"(v)); return r;
}
__device__ __forceinline__ float fast_rcp(float v) {
    float r; asm("rcp.approx.ftz.f32 %0, %1;" : "=f"(r) : "f"(v)); return r;
}
__device__ __forceinline__ float fast_floor(float v) {
    float r; asm("cvt.rmi.f32.f32 %0, %1;" : "=f"(r) : "f"(v)); return r;
}

// Exact fp32 GMM Hyvarinen score; constants from smem (broadcast LDS).
__device__ __forceinline__ float hscore_exact_s(
    float x,
    const float* __restrict__ sAl, const float* __restrict__ sBe,
    const float* __restrict__ sGa, const float* __restrict__ sIv,
    const float* __restrict__ sNm)
{
    float x2 = x * x;
    float mp = 0.f, ms = 0.f, dd = 0.f;
#pragma unroll
    for (int k = 0; k < K; k++) {
        float t = fmaf(sGa[k], x2, fmaf(sBe[k], x, sAl[k])); // log2 p_k
        float p = fast_ex2(t);
        float s = fmaf(sIv[k], x, sNm[k]);     // iv*(x-mu)
        float u = fmaf(s, s, -sIv[k]);
        mp += p;
        ms = fmaf(p, s, ms);
        dd = fmaf(p, u, dd);
    }
    float r  = fast_rcp(mp);
    float dl = ms * r;
    float g  = dd * r;
    return fmaf(-0.5f, dl * dl, g);
}

// Linear interpolation: one LDS.64 (256B/warp, ~2x fewer crossbar phases
// than the previous LDS.128 cubic gather) + sub + fma.
__device__ __forceinline__ float interp1(float x, const float2* __restrict__ sL) {
    const float INV_H = (float)(TBL - 1) / XRANGE_F;
    const float OFF   = -XMIN_F * INV_H;
    float u  = fmaf(x, INV_H, OFF);
    float fl = fast_floor(u);
    float f  = u - fl;
    int   i  = (int)fl;
    i = min(max(i, 0), TBL - 2);
    float2 q = sL[i];                          // {h_i, h_{i+1}}
    return fmaf(f, q.y - q.x, q.x);
}

__global__ void __launch_bounds__(THREADS)
gmm_fused_kernel(const float4* __restrict__ x4, float4* __restrict__ out4,
                 const float* __restrict__ mean, const float* __restrict__ logvar,
                 const float* __restrict__ logweight, int n4)
{
    __shared__ float  sAl[K], sBe[K], sGa[K], sIv[K], sNm[K];
    __shared__ float  sT[TBL];                 // scalar taps, 8 KB
    __shared__ float2 sL[TBL];                 // redundant pairs, 16 KB

    int tid = threadIdx.x;

    // First data load in flight before/during the table build.
    int stride = gridDim.x * THREADS;
    int idx = blockIdx.x * THREADS + tid;
    float4 cur;
    bool have = idx < n4;
    if (have) cur = x4[idx];

    // --- constants ---
    if (tid < K) {
        float mu = mean[tid], lv = logvar[tid], lw = logweight[tid];
        float iv = __expf(-lv);
        float a2 = (lw - 0.5f * (lv + LOG2PI)) * LOG2E;
        float z  = 0.5f * LOG2E * iv;
        sAl[tid] = a2 - z * mu * mu;
        sBe[tid] = 2.f * z * mu;
        sGa[tid] = -z;
        sIv[tid] = iv;
        sNm[tid] = -iv * mu;
    }
    __syncthreads();

    // --- table build: TBL taps, 8 per thread ---
    {
        const float H = XRANGE_F / (float)(TBL - 1);
#pragma unroll
        for (int r = 0; r < TBL / THREADS; r++) {
            int j = tid + r * THREADS;
            sT[j] = hscore_exact_s(fmaf((float)j, H, XMIN_F), sAl, sBe, sGa, sIv, sNm);
        }
    }
    __syncthreads();
#pragma unroll
    for (int r = 0; r < TBL / THREADS; r++) {
        int j = tid + r * THREADS;
        float hi = (j + 1 < TBL) ? sT[j + 1] : sT[TBL - 1];
        sL[j] = make_float2(sT[j], hi);
    }
    __syncthreads();

    // --- software-pipelined streaming loop ---
    while (have) {
        int nidx = idx + stride;
        float4 nxt;
        bool nhave = nidx < n4;
        if (nhave) nxt = x4[nidx];             // prefetch next tile

        float4 ov;
        ov.x = interp1(cur.x, sL);
        ov.y = interp1(cur.y, sL);
        ov.z = interp1(cur.z, sL);
        ov.w = interp1(cur.w, sL);
        out4[idx] = ov;

        idx = nidx; cur = nxt; have = nhave;
    }
}

extern "C" void kernel_launch(void* const* d_in, const int* in_sizes, int n_in,
                              void* d_out, int out_size) {
    const float* x         = (const float*)d_in[0];
    const float* mean      = (const float*)d_in[1];
    const float* logvar    = (const float*)d_in[2];
    const float* logweight = (const float*)d_in[3];
    float* out = (float*)d_out;

    int n  = in_sizes[0];
    int n4 = n >> 2;

    gmm_fused_kernel<<<NBLOCKS, THREADS>>>(
        (const float4*)x, (float4*)out, mean, logvar, logweight, n4);
}

// round 17
// speedup vs baseline: 1.5468x; 1.5468x over previous
#include <cuda_runtime.h>

#define K 8
#define TBL 512
#define THREADS 256
#define BLOCKS_PER_SM 6
#define NBLOCKS (148 * BLOCKS_PER_SM)
#define XMIN_F (-6.0f)
#define XRANGE_F 12.0f
#define LOG2PI 1.8378770664093453f
#define LOG2E  1.4426950408889634f

__device__ __forceinline__ float fast_ex2(float v) {
    float r; asm("ex2.approx.ftz.f32 %0, %1;" : "=f"(r) : "f"(v)); return r;
}
__device__ __forceinline__ float fast_rcp(float v) {
    float r; asm("rcp.approx.ftz.f32 %0, %1;" : "=f"(r) : "f"(v)); return r;
}
__device__ __forceinline__ float fast_floor(float v) {
    float r; asm("cvt.rmi.f32.f32 %0, %1;" : "=f"(r) : "f"(v)); return r;
}

// Exact fp32 GMM Hyvarinen score; constants from smem (broadcast LDS).
__device__ __forceinline__ float hscore_exact_s(
    float x,
    const float* __restrict__ sAl, const float* __restrict__ sBe,
    const float* __restrict__ sGa, const float* __restrict__ sIv,
    const float* __restrict__ sNm)
{
    float x2 = x * x;
    float mp = 0.f, ms = 0.f, dd = 0.f;
#pragma unroll
    for (int k = 0; k < K; k++) {
        float t = fmaf(sGa[k], x2, fmaf(sBe[k], x, sAl[k])); // log2 p_k
        float p = fast_ex2(t);
        float s = fmaf(sIv[k], x, sNm[k]);     // iv*(x-mu)
        float u = fmaf(s, s, -sIv[k]);
        mp += p;
        ms = fmaf(p, s, ms);
        dd = fmaf(p, u, dd);
    }
    float r  = fast_rcp(mp);
    float dl = ms * r;
    float g  = dd * r;
    return fmaf(-0.5f, dl * dl, g);
}

// Linear interpolation: one LDS.64 + sub + fma (short dependent chain).
__device__ __forceinline__ float interp1(float x, const float2* __restrict__ sL) {
    const float INV_H = (float)(TBL - 1) / XRANGE_F;
    const float OFF   = -XMIN_F * INV_H;
    float u  = fmaf(x, INV_H, OFF);
    float fl = fast_floor(u);
    float f  = u - fl;
    int   i  = (int)fl;
    i = min(max(i, 0), TBL - 2);
    float2 q = sL[i];                          // {h_i, h_{i+1}}
    return fmaf(f, q.y - q.x, q.x);
}

__global__ void __launch_bounds__(THREADS, BLOCKS_PER_SM)
gmm_fused_kernel(const float4* __restrict__ x4, float4* __restrict__ out4,
                 const float* __restrict__ mean, const float* __restrict__ logvar,
                 const float* __restrict__ logweight, int n4)
{
    __shared__ float  sAl[K], sBe[K], sGa[K], sIv[K], sNm[K];
    __shared__ float  sT[TBL];                 // scalar taps, 2 KB
    __shared__ float2 sL[TBL];                 // redundant pairs, 4 KB

    int tid = threadIdx.x;

    // First data load in flight before/during the table build.
    int stride = gridDim.x * THREADS;
    int idx = blockIdx.x * THREADS + tid;
    float4 cur;
    bool have = idx < n4;
    if (have) cur = x4[idx];

    // --- constants ---
    if (tid < K) {
        float mu = mean[tid], lv = logvar[tid], lw = logweight[tid];
        float iv = __expf(-lv);
        float a2 = (lw - 0.5f * (lv + LOG2PI)) * LOG2E;
        float z  = 0.5f * LOG2E * iv;
        sAl[tid] = a2 - z * mu * mu;
        sBe[tid] = 2.f * z * mu;
        sGa[tid] = -z;
        sIv[tid] = iv;
        sNm[tid] = -iv * mu;
    }
    __syncthreads();

    // --- table build: 512 taps, 2 per thread ---
    {
        const float H = XRANGE_F / (float)(TBL - 1);
#pragma unroll
        for (int r = 0; r < TBL / THREADS; r++) {
            int j = tid + r * THREADS;
            sT[j] = hscore_exact_s(fmaf((float)j, H, XMIN_F), sAl, sBe, sGa, sIv, sNm);
        }
    }
    __syncthreads();
#pragma unroll
    for (int r = 0; r < TBL / THREADS; r++) {
        int j = tid + r * THREADS;
        float hi = (j + 1 < TBL) ? sT[j + 1] : sT[TBL - 1];
        sL[j] = make_float2(sT[j], hi);
    }
    __syncthreads();

    // --- software-pipelined streaming loop ---
    while (have) {
        int nidx = idx + stride;
        float4 nxt;
        bool nhave = nidx < n4;
        if (nhave) nxt = x4[nidx];             // prefetch next tile

        float4 ov;
        ov.x = interp1(cur.x, sL);
        ov.y = interp1(cur.y, sL);
        ov.z = interp1(cur.z, sL);
        ov.w = interp1(cur.w, sL);
        out4[idx] = ov;

        idx = nidx; cur = nxt; have = nhave;
    }
}

extern "C" void kernel_launch(void* const* d_in, const int* in_sizes, int n_in,
                              void* d_out, int out_size) {
    const float* x         = (const float*)d_in[0];
    const float* mean      = (const float*)d_in[1];
    const float* logvar    = (const float*)d_in[2];
    const float* logweight = (const float*)d_in[3];
    float* out = (float*)d_out;

    int n  = in_sizes[0];
    int n4 = n >> 2;

    gmm_fused_kernel<<<NBLOCKS, THREADS>>>(
        (const float4*)x, (float4*)out, mean, logvar, logweight, n4);
}